// round 5
// baseline (speedup 1.0000x reference)
#include <cuda_runtime.h>
#include <cstddef>

// VectorQuantizer: z (16,128,64,64) f32, codebook (1024,128) f32.
// N = 65536 tokens of C=128; K=1024 codes.
// Outputs: z_q_st (8388608 f32, NCHW), vq_loss, usage -> d_out concatenated.
//
// Numerics: replicate the reference's fp32 dataflow exactly:
//   s_tk = fl( fl(A_t + B_k) - 2*M_tk ),  A=||z||^2, B=||e||^2, M=z.e
// so that lattice-quantization ties (ulp(128)=1.5e-5) resolve identically.

#define C_   128
#define K_   1024
#define NTOK 65536
#define TOK  64      // tokens per CTA
#define KC   128     // codes per chunk
#define EST  132     // padded eT row stride (floats)
#define NBLK (NTOK / TOK)   // 1024

__device__ float g_bnorm[K_];     // ||e_k||^2  (rounded like jnp.sum(e**2))
__device__ int   g_used[K_];
__device__ float g_partial[NBLK]; // per-block loss partial sums

// ---------------------------------------------------------------------------
// init: zero usage flags, compute codebook row norms with separate rounding
// of each square (matches reference's elementwise square-then-sum).
// ---------------------------------------------------------------------------
__global__ void vq_init(const float* __restrict__ cb) {
    int k = blockIdx.x * blockDim.x + threadIdx.x;
    if (k < K_) {
        g_used[k] = 0;
        const float* row = cb + (size_t)k * C_;
        float s = 0.f;
        for (int c = 0; c < C_; ++c) {
            float q = __fmul_rn(row[c], row[c]);
            s = __fadd_rn(s, q);
        }
        g_bnorm[k] = s;
    }
}

// ---------------------------------------------------------------------------
// main: per 64-token tile, argmin over 1024 codes of fl(fl(A+B)-2M),
// then fused epilogue: gather winning code, write z_q_st, accumulate loss.
// ---------------------------------------------------------------------------
__global__ __launch_bounds__(256, 2) void vq_main(const float* __restrict__ z,
                                                  const float* __restrict__ cb,
                                                  float* __restrict__ out) {
    extern __shared__ float smem[];
    float* zT  = smem;               // [C_][TOK]   (c-major, stride TOK)
    float* a_s = smem + C_ * TOK;    // [TOK]       token norms ||z_t||^2
    float* eT  = a_s + TOK;          // [C_][EST]   (c-major, padded stride)
    // reduction arrays overlay eT after the chunk loop:
    float* red_s = eT;                       // [TOK][16]
    int*   red_k = (int*)(eT + TOK * 16);    // [TOK][16]
    int*   idx_s = (int*)(eT + TOK * 32);    // [TOK]

    const int tid = threadIdx.x;
    const int tx  = tid & 15;   // 16 code-groups of 8
    const int ty  = tid >> 4;   // 16 token-groups of 4

    const int tile = blockIdx.x * TOK;     // no b-straddle: 64 | 4096
    const int b    = tile >> 12;
    const int hw   = tile & 4095;
    const float* zbase = z + ((size_t)b * C_) * 4096 + hw;

    // stage z tile transposed (c-major); global reads coalesced
    for (int i = tid; i < C_ * TOK; i += 256) {
        int c = i >> 6, t = i & 63;
        zT[c * TOK + t] = zbase[(size_t)c * 4096 + t];
    }
    __syncthreads();

    // token norms A_t (separate rounding of squares, like jnp.sum(z**2))
    if (tid < TOK) {
        float a = 0.f;
        for (int c = 0; c < C_; ++c) {
            float v = zT[c * TOK + tid];
            float q = __fmul_rn(v, v);
            a = __fadd_rn(a, q);
        }
        a_s[tid] = a;
    }
    // (visible after the __syncthreads inside the first chunk iteration)

    float best[4];
    int   bk[4];
    #pragma unroll
    for (int i = 0; i < 4; ++i) { best[i] = 3.4e38f; bk[i] = 0; }

    for (int ch = 0; ch < K_ / KC; ++ch) {
        const int kb = ch * KC;
        // stage codebook chunk transposed
        for (int i = tid; i < KC * C_; i += 256) {
            int k = i >> 7, c = i & 127;
            eT[c * EST + k] = cb[(size_t)(kb + k) * C_ + c];
        }
        __syncthreads();

        float acc[4][8];
        #pragma unroll
        for (int i = 0; i < 4; ++i)
            #pragma unroll
            for (int j = 0; j < 8; ++j) acc[i][j] = 0.f;

        const float* zp = zT + ty * 4;
        const float* ep = eT + tx * 8;
        #pragma unroll 4
        for (int c = 0; c < C_; ++c) {
            float4 zv = *(const float4*)(zp + (size_t)c * TOK);
            float4 e0 = *(const float4*)(ep + (size_t)c * EST);
            float4 e1 = *(const float4*)(ep + (size_t)c * EST + 4);
            float zz[4] = {zv.x, zv.y, zv.z, zv.w};
            float ee[8] = {e0.x, e0.y, e0.z, e0.w, e1.x, e1.y, e1.z, e1.w};
            #pragma unroll
            for (int i = 0; i < 4; ++i)
                #pragma unroll
                for (int j = 0; j < 8; ++j)
                    acc[i][j] = fmaf(zz[i], ee[j], acc[i][j]);
        }

        // running argmin with reference-identical rounding:
        //   s = fl( fl(A + B) - 2*M )   (2*M exact, single-rounded subtract)
        #pragma unroll
        for (int j = 0; j < 8; ++j) {
            int k = kb + tx * 8 + j;
            float bn = __ldg(&g_bnorm[k]);
            #pragma unroll
            for (int i = 0; i < 4; ++i) {
                float t1 = __fadd_rn(a_s[ty * 4 + i], bn);
                float s  = __fmaf_rn(-2.f, acc[i][j], t1);
                if (s < best[i] || (s == best[i] && k < bk[i])) { best[i] = s; bk[i] = k; }
            }
        }
        __syncthreads();  // before eT is overwritten next chunk
    }

    // cross-tx reduction: 16 candidates per token (lowest-k tie-break)
    #pragma unroll
    for (int i = 0; i < 4; ++i) {
        int t = ty * 4 + i;
        red_s[t * 16 + tx] = best[i];
        red_k[t * 16 + tx] = bk[i];
    }
    __syncthreads();
    if (tid < TOK) {
        float bs = red_s[tid * 16];
        int   bi = red_k[tid * 16];
        #pragma unroll
        for (int x = 1; x < 16; ++x) {
            float s = red_s[tid * 16 + x];
            int   k = red_k[tid * 16 + x];
            if (s < bs || (s == bs && k < bi)) { bs = s; bi = k; }
        }
        idx_s[tid] = bi;
        g_used[bi] = 1;   // racy but idempotent -> deterministic
    }
    __syncthreads();

    // epilogue: z_q_st = fl(z + fl(e - z)) elementwise (matches reference);
    // loss partial = sum fl(e-z)^2
    float* obase = out + ((size_t)b * C_) * 4096 + hw;
    float lsum = 0.f;
    for (int i = tid; i < C_ * TOK; i += 256) {
        int c = i >> 6, t = i & 63;
        float e  = __ldg(cb + (size_t)idx_s[t] * C_ + c);
        float zz = zT[c * TOK + t];
        float d  = __fsub_rn(e, zz);
        obase[(size_t)c * 4096 + t] = __fadd_rn(zz, d);
        lsum = fmaf(d, d, lsum);
    }
    #pragma unroll
    for (int o = 16; o; o >>= 1) lsum += __shfl_xor_sync(0xffffffffu, lsum, o);
    __shared__ float wsum[8];
    if ((tid & 31) == 0) wsum[tid >> 5] = lsum;
    __syncthreads();
    if (tid == 0) {
        float s = 0.f;
        #pragma unroll
        for (int w = 0; w < 8; ++w) s += wsum[w];
        g_partial[blockIdx.x] = s;
    }
}

// ---------------------------------------------------------------------------
// finalize: vq_loss = 1.25 * mean, usage = count(used)/K
// ---------------------------------------------------------------------------
__global__ void vq_final(float* __restrict__ out, int out_size) {
    __shared__ double ds[256];
    __shared__ int    ci[256];
    int tid = threadIdx.x;
    double s = 0.0;
    int cnt = 0;
    for (int i = tid; i < NBLK; i += 256) s += (double)g_partial[i];
    for (int i = tid; i < K_;   i += 256) cnt += (g_used[i] != 0);
    ds[tid] = s; ci[tid] = cnt;
    __syncthreads();
    for (int o = 128; o; o >>= 1) {
        if (tid < o) { ds[tid] += ds[tid + o]; ci[tid] += ci[tid + o]; }
        __syncthreads();
    }
    if (tid == 0) {
        double numel = (double)(out_size - 2);
        double m = ds[0] / numel;
        out[out_size - 2] = (float)(1.25 * m);
        out[out_size - 1] = (float)ci[0] / (float)K_;
    }
}

extern "C" void kernel_launch(void* const* d_in, const int* in_sizes, int n_in,
                              void* d_out, int out_size) {
    (void)in_sizes; (void)n_in;
    const float* z  = (const float*)d_in[0];
    const float* cb = (const float*)d_in[1];
    float* out = (float*)d_out;

    const int smem_bytes = (C_ * TOK + TOK + C_ * EST) * 4;  // 100608
    cudaFuncSetAttribute(vq_main, cudaFuncAttributeMaxDynamicSharedMemorySize, smem_bytes);

    vq_init<<<(K_ + 255) / 256, 256>>>(cb);
    vq_main<<<NBLK, 256, smem_bytes>>>(z, cb, out);
    vq_final<<<1, 256>>>(out, out_size);
}

// round 11
// speedup vs baseline: 2.3881x; 2.3881x over previous
#include <cuda_runtime.h>
#include <cuda_bf16.h>
#include <cstdint>
#include <cstddef>

// VectorQuantizer via warp-level bf16 HMMA (mma.sync, portable sm_103 target)
// + exact fp32 lattice refinement for bit-identical argmin.
// z (16,128,64,64) f32, codebook (1024,128) f32.

#define C_     128
#define K_     1024
#define NTOK   65536
#define TOK    128
#define NBLK   (NTOK / TOK)   // 512
#define NCHUNK 32             // 32 codes per chunk
#define MARGIN 3e-5f

#define ROWB   272            // 136 bf16 padded row stride (conflict-free ldmatrix)
#define OFF_ZH 0
#define OFF_ZL 34816
#define OFF_B  69632
#define BUFSZ  17536          // eh 8704 | el 8704 | bn 128
#define OFF_PV 69632          // reuse B region after mainloop
#define OFF_PK 75776
#define OFF_IDX 104704
#define OFF_WS  105216
#define SMEM_TOTAL 105248

__device__ float g_bnorm[K_];
__device__ int   g_used[K_];
__device__ float g_partial[NBLK];
__device__ unsigned short g_cbh[K_ * C_];   // bf16 hi
__device__ unsigned short g_cbl[K_ * C_];   // bf16 lo

// ------------------------------------------------------------------ helpers
__device__ __forceinline__ uint32_t smem_u32(const void* p) {
    uint32_t a;
    asm("{ .reg .u64 t; cvta.to.shared.u64 t, %1; cvt.u32.u64 %0, t; }" : "=r"(a) : "l"(p));
    return a;
}
__device__ __forceinline__ void cpa16(uint32_t dst, const void* src) {
    asm volatile("cp.async.cg.shared.global [%0], [%1], 16;" :: "r"(dst), "l"(src) : "memory");
}
#define CPA_COMMIT() asm volatile("cp.async.commit_group;" ::: "memory")
#define CPA_WAIT1()  asm volatile("cp.async.wait_group 1;" ::: "memory")
#define CPA_WAIT0()  asm volatile("cp.async.wait_group 0;" ::: "memory")
#define LDSM4(d0,d1,d2,d3,a) \
    asm volatile("ldmatrix.sync.aligned.m8n8.x4.shared.b16 {%0,%1,%2,%3}, [%4];" \
                 : "=r"(d0),"=r"(d1),"=r"(d2),"=r"(d3) : "r"(a))
#define LDSM2(d0,d1,a) \
    asm volatile("ldmatrix.sync.aligned.m8n8.x2.shared.b16 {%0,%1}, [%2];" \
                 : "=r"(d0),"=r"(d1) : "r"(a))
__device__ __forceinline__ void mma_bf16(float acc[4], const uint32_t a[4],
                                         uint32_t b0, uint32_t b1) {
    asm volatile("mma.sync.aligned.m16n8k16.row.col.f32.bf16.bf16.f32 "
                 "{%0,%1,%2,%3},{%4,%5,%6,%7},{%8,%9},{%0,%1,%2,%3};"
                 : "+f"(acc[0]), "+f"(acc[1]), "+f"(acc[2]), "+f"(acc[3])
                 : "r"(a[0]), "r"(a[1]), "r"(a[2]), "r"(a[3]), "r"(b0), "r"(b1));
}
// running top-3 (value,index), ascending
#define UPD3(V1,V2,V3,I1,I2,I3,s,kk) do {                                  \
    if ((s) < V1)      { V3=V2; I3=I2; V2=V1; I2=I1; V1=(s); I1=(kk); }    \
    else if ((s) < V2) { V3=V2; I3=I2; V2=(s); I2=(kk); }                  \
    else if ((s) < V3) { V3=(s); I3=(kk); }                                \
} while (0)

// ------------------------------------------------------------------ prep
// bnorms (bit-identical serial order), usage reset, codebook bf16 hi/lo bake.
__global__ __launch_bounds__(256) void vq_prep(const float* __restrict__ cb) {
    __shared__ float sc[64 * 129];
    const int tid = threadIdx.x;
    const int row0 = blockIdx.x * 64;
    for (int i = tid; i < 64 * 128; i += 256) {
        int r = i >> 7, c = i & 127;
        sc[r * 129 + c] = cb[(size_t)(row0 + r) * C_ + c];
    }
    __syncthreads();
    if (tid < 64) {
        float s = 0.f;
        for (int c = 0; c < C_; ++c) {
            float v = sc[tid * 129 + c];
            s = __fadd_rn(s, __fmul_rn(v, v));
        }
        g_bnorm[row0 + tid] = s;
        g_used[row0 + tid] = 0;
    }
    for (int i = tid; i < 64 * 128; i += 256) {
        int r = i >> 7, c = i & 127;
        float v = sc[r * 129 + c];
        __nv_bfloat16 h = __float2bfloat16(v);
        __nv_bfloat16 l = __float2bfloat16(v - __bfloat162float(h));
        g_cbh[(size_t)(row0 + r) * C_ + c] = __bfloat16_as_ushort(h);
        g_cbl[(size_t)(row0 + r) * C_ + c] = __bfloat16_as_ushort(l);
    }
}

// ------------------------------------------------------------------ main
__global__ __launch_bounds__(256, 2)
void vq_main(const float* __restrict__ z, const float* __restrict__ cb,
             float* __restrict__ out) {
    extern __shared__ char smem[];
    const uint32_t smem_u = smem_u32(smem);
    const int tid = threadIdx.x;
    const int wid = tid >> 5, lane = tid & 31;

    const int tile = blockIdx.x * TOK;
    const int b = tile >> 12, hw = tile & 4095;
    const float* zbase = z + ((size_t)b * C_) * 4096 + hw;

    unsigned short* sZh = (unsigned short*)(smem + OFF_ZH);
    unsigned short* sZl = (unsigned short*)(smem + OFF_ZL);
    int*   idx_s = (int*)(smem + OFF_IDX);
    float* wsum  = (float*)(smem + OFF_WS);
    float* pv    = (float*)(smem + OFF_PV);
    int*   pk    = (int*)(smem + OFF_PK);

    // ---- stage z -> zh/zl bf16, padded row-major [token][c] ----
    {
        const int t = tid & 127, h = tid >> 7;
        for (int it = 0; it < 64; ++it) {
            int c = it * 2 + h;
            float v = zbase[(size_t)c * 4096 + t];
            __nv_bfloat16 hi = __float2bfloat16(v);
            __nv_bfloat16 lo = __float2bfloat16(v - __bfloat162float(hi));
            sZh[t * 136 + c] = __bfloat16_as_ushort(hi);
            sZl[t * 136 + c] = __bfloat16_as_ushort(lo);
        }
    }

    // ---- B chunk staging (cp.async): 32 codes -> eh|el|bn ----
    #define STAGE(ch, buf) do {                                                     \
        uint32_t _d = smem_u + OFF_B + (buf) * BUFSZ;                               \
        for (int _i = tid; _i < 512; _i += 256) {                                   \
            int _r = _i >> 4, _cs = _i & 15;                                        \
            const size_t _g = (size_t)((ch) * NCHUNK + _r) * C_ + _cs * 8;          \
            cpa16(_d + _r * ROWB + _cs * 16, g_cbh + _g);                           \
            cpa16(_d + 8704 + _r * ROWB + _cs * 16, g_cbl + _g);                    \
        }                                                                           \
        if (tid < 8) cpa16(_d + 17408 + tid * 16, g_bnorm + (ch) * NCHUNK + tid * 4); \
    } while (0)

    __syncthreads();   // zh/zl visible before ldmatrix

    // ---- cache A fragments for this warp's 16 tokens (whole mainloop) ----
    uint32_t Ah[8][4], Al[8][4];
    {
        uint32_t aZh = smem_u + OFF_ZH + (wid * 16 + (lane & 15)) * ROWB + (lane >> 4) * 16;
        uint32_t aZl = smem_u + OFF_ZL + (wid * 16 + (lane & 15)) * ROWB + (lane >> 4) * 16;
        #pragma unroll
        for (int k = 0; k < 8; ++k) {
            LDSM4(Ah[k][0], Ah[k][1], Ah[k][2], Ah[k][3], aZh + k * 32);
            LDSM4(Al[k][0], Al[k][1], Al[k][2], Al[k][3], aZl + k * 32);
        }
    }

    STAGE(0, 0);
    CPA_COMMIT();

    float v01 = 3e38f, v02 = 3e38f, v03 = 3e38f;   // top-3 row0
    float v11 = 3e38f, v12 = 3e38f, v13 = 3e38f;   // top-3 row1 (+8)
    int   i01 = 0, i02 = 0, i03 = 0, i11 = 0, i12 = 0, i13 = 0;

    for (int ch = 0; ch < K_ / NCHUNK; ++ch) {
        const int buf = ch & 1;
        if (ch + 1 < K_ / NCHUNK) { STAGE(ch + 1, buf ^ 1); CPA_COMMIT(); CPA_WAIT1(); }
        else                      { CPA_WAIT0(); }
        __syncthreads();

        const uint32_t behB = smem_u + OFF_B + buf * BUFSZ;
        const uint32_t belB = behB + 8704;
        const char* bnB = smem + OFF_B + buf * BUFSZ + 17408;

        #pragma unroll
        for (int nb = 0; nb < 4; ++nb) {
            float acc[4] = {0.f, 0.f, 0.f, 0.f};
            uint32_t bah = behB + (nb * 8 + (lane & 7)) * ROWB + ((lane >> 3) & 1) * 16;
            uint32_t bal = belB + (nb * 8 + (lane & 7)) * ROWB + ((lane >> 3) & 1) * 16;
            #pragma unroll
            for (int k = 0; k < 8; ++k) {
                uint32_t bh0, bh1, bl0, bl1;
                LDSM2(bh0, bh1, bah + k * 32);
                LDSM2(bl0, bl1, bal + k * 32);
                mma_bf16(acc, Ah[k], bh0, bh1);   // zh.eh
                mma_bf16(acc, Al[k], bh0, bh1);   // zl.eh
                mma_bf16(acc, Ah[k], bl0, bl1);   // zh.el
            }
            float2 bnv = *(const float2*)(bnB + (nb * 8 + 2 * (lane & 3)) * 4);
            int col = ch * NCHUNK + nb * 8 + 2 * (lane & 3);
            float s;
            s = __fmaf_rn(-2.f, acc[0], bnv.x); UPD3(v01, v02, v03, i01, i02, i03, s, col);
            s = __fmaf_rn(-2.f, acc[1], bnv.y); UPD3(v01, v02, v03, i01, i02, i03, s, col + 1);
            s = __fmaf_rn(-2.f, acc[2], bnv.x); UPD3(v11, v12, v13, i11, i12, i13, s, col);
            s = __fmaf_rn(-2.f, acc[3], bnv.y); UPD3(v11, v12, v13, i11, i12, i13, s, col + 1);
        }
        __syncthreads();   // reads of buf done before it is restaged
    }

    // ---- publish candidates: 4 lanes x top-3 = 12 per token ----
    {
        int t0 = wid * 16 + (lane >> 2);
        int slot = (lane & 3) * 3;
        pv[(slot + 0) * 128 + t0] = v01;  pk[(slot + 0) * 128 + t0] = i01;
        pv[(slot + 1) * 128 + t0] = v02;  pk[(slot + 1) * 128 + t0] = i02;
        pv[(slot + 2) * 128 + t0] = v03;  pk[(slot + 2) * 128 + t0] = i03;
        int t1 = t0 + 8;
        pv[(slot + 0) * 128 + t1] = v11;  pk[(slot + 0) * 128 + t1] = i11;
        pv[(slot + 1) * 128 + t1] = v12;  pk[(slot + 1) * 128 + t1] = i12;
        pv[(slot + 2) * 128 + t1] = v13;  pk[(slot + 2) * 128 + t1] = i13;
    }
    __syncthreads();

    // ---- exact fp32 lattice refinement (reference-identical rounding) ----
    if (tid < 128) {
        const int t = tid;
        float A = 0.f;
        #pragma unroll 8
        for (int c = 0; c < C_; ++c) {
            float v = zbase[(size_t)c * 4096 + t];
            A = __fadd_rn(A, __fmul_rn(v, v));
        }
        float vmin = 3.4e38f;
        #pragma unroll
        for (int q = 0; q < 12; ++q) vmin = fminf(vmin, pv[q * 128 + t]);
        float bs = 3.4e38f;
        int   bi = 0x7fffffff;
        for (int q = 0; q < 12; ++q) {
            if (pv[q * 128 + t] <= vmin + MARGIN) {
                int k = pk[q * 128 + t];
                const float* e = cb + (size_t)k * C_;
                float M = 0.f;
                #pragma unroll 8
                for (int c = 0; c < C_; ++c)
                    M = __fmaf_rn(zbase[(size_t)c * 4096 + t], __ldg(e + c), M);
                float s = __fmaf_rn(-2.f, M, __fadd_rn(A, __ldg(&g_bnorm[k])));
                if (s < bs || (s == bs && k < bi)) { bs = s; bi = k; }
            }
        }
        idx_s[t] = bi;
        g_used[bi] = 1;   // racy but idempotent -> deterministic
    }
    __syncthreads();

    // ---- epilogue: z_q_st = fl(z + fl(e - z)); loss partial ----
    float* obase = out + ((size_t)b * C_) * 4096 + hw;
    float lsum = 0.f;
    for (int i = tid; i < C_ * TOK; i += 256) {
        int c = i >> 7, t = i & 127;
        float e  = __ldg(cb + (size_t)idx_s[t] * C_ + c);
        float zz = zbase[(size_t)c * 4096 + t];
        float d  = __fsub_rn(e, zz);
        obase[(size_t)c * 4096 + t] = __fadd_rn(zz, d);
        lsum = __fmaf_rn(d, d, lsum);
    }
    #pragma unroll
    for (int o = 16; o; o >>= 1) lsum += __shfl_xor_sync(0xffffffffu, lsum, o);
    if ((tid & 31) == 0) wsum[wid] = lsum;
    __syncthreads();
    if (tid == 0) {
        float s = 0.f;
        #pragma unroll
        for (int w = 0; w < 8; ++w) s += wsum[w];
        g_partial[blockIdx.x] = s;
    }
}

// ------------------------------------------------------------------ finalize
__global__ void vq_final(float* __restrict__ out, int out_size) {
    __shared__ double ds[256];
    __shared__ int    ci[256];
    int tid = threadIdx.x;
    double s = 0.0;
    int cnt = 0;
    for (int i = tid; i < NBLK; i += 256) s += (double)g_partial[i];
    for (int i = tid; i < K_;   i += 256) cnt += (g_used[i] != 0);
    ds[tid] = s; ci[tid] = cnt;
    __syncthreads();
    for (int o = 128; o; o >>= 1) {
        if (tid < o) { ds[tid] += ds[tid + o]; ci[tid] += ci[tid + o]; }
        __syncthreads();
    }
    if (tid == 0) {
        double m = ds[0] / (double)(out_size - 2);
        out[out_size - 2] = (float)(1.25 * m);
        out[out_size - 1] = (float)ci[0] / (float)K_;
    }
}

extern "C" void kernel_launch(void* const* d_in, const int* in_sizes, int n_in,
                              void* d_out, int out_size) {
    (void)in_sizes; (void)n_in;
    const float* z  = (const float*)d_in[0];
    const float* cb = (const float*)d_in[1];
    float* out = (float*)d_out;

    cudaFuncSetAttribute(vq_main, cudaFuncAttributeMaxDynamicSharedMemorySize, SMEM_TOTAL);

    vq_prep<<<16, 256>>>(cb);
    vq_main<<<NBLK, 256, SMEM_TOTAL>>>(z, cb, out);
    vq_final<<<1, 256>>>(out, out_size);
}

// round 12
// speedup vs baseline: 3.0981x; 1.2973x over previous
#include <cuda_runtime.h>
#include <cuda_fp16.h>
#include <cstdint>
#include <cstddef>

// VectorQuantizer: single-pass fp16 HMMA candidate GEMM (deterministic error
// bound via tiny codebook range) + exact fp32 lattice refinement.
// z (16,128,64,64) f32, codebook (1024,128) f32.

#define C_     128
#define K_     1024
#define NTOK   65536
#define TOK    256
#define NBLK   (NTOK / TOK)   // 256
#define NCC    64             // codes per chunk
#define NCHUNK (K_ / NCC)     // 16
#define MARGIN 4e-4f

#define ROWB   272            // 136 halves padded row stride (conflict-free ldmatrix)
#define OFF_Z   0             // 256 x 272            = 69632
#define OFF_B   69632         // 2 x (64*272 + 256)   = 35328
#define BUFSZ   17664
#define OFF_PV  104960        // 12 x 256 x 4 = 12288
#define OFF_PK  117248        // 12288
#define OFF_IDX 129536        // 1024
#define OFF_WS  130560        // 64
#define SMEM_TOTAL 130624

__device__ float g_bnorm[K_];
__device__ int   g_used[K_];
__device__ float g_partial[NBLK];
__device__ __align__(16) unsigned short g_cbq[K_ * C_];   // fp16 codebook

// ------------------------------------------------------------------ helpers
__device__ __forceinline__ uint32_t smem_u32(const void* p) {
    uint32_t a;
    asm("{ .reg .u64 t; cvta.to.shared.u64 t, %1; cvt.u32.u64 %0, t; }" : "=r"(a) : "l"(p));
    return a;
}
__device__ __forceinline__ void cpa16(uint32_t dst, const void* src) {
    asm volatile("cp.async.cg.shared.global [%0], [%1], 16;" :: "r"(dst), "l"(src) : "memory");
}
#define CPA_COMMIT() asm volatile("cp.async.commit_group;" ::: "memory")
#define CPA_WAIT1()  asm volatile("cp.async.wait_group 1;" ::: "memory")
#define CPA_WAIT0()  asm volatile("cp.async.wait_group 0;" ::: "memory")
#define LDSM4(d0,d1,d2,d3,a) \
    asm volatile("ldmatrix.sync.aligned.m8n8.x4.shared.b16 {%0,%1,%2,%3}, [%4];" \
                 : "=r"(d0),"=r"(d1),"=r"(d2),"=r"(d3) : "r"(a))
__device__ __forceinline__ void mma_f16(float acc[4], const uint32_t a[4],
                                        uint32_t b0, uint32_t b1) {
    asm volatile("mma.sync.aligned.m16n8k16.row.col.f32.f16.f16.f32 "
                 "{%0,%1,%2,%3},{%4,%5,%6,%7},{%8,%9},{%0,%1,%2,%3};"
                 : "+f"(acc[0]), "+f"(acc[1]), "+f"(acc[2]), "+f"(acc[3])
                 : "r"(a[0]), "r"(a[1]), "r"(a[2]), "r"(a[3]), "r"(b0), "r"(b1));
}
#define UPD3(V1,V2,V3,I1,I2,I3,s,kk) do {                                  \
    if ((s) < V1)      { V3=V2; I3=I2; V2=V1; I2=I1; V1=(s); I1=(kk); }    \
    else if ((s) < V2) { V3=V2; I3=I2; V2=(s); I2=(kk); }                  \
    else if ((s) < V3) { V3=(s); I3=(kk); }                                \
} while (0)

// ------------------------------------------------------------------ prep
// exact serial bnorms, usage reset, fp16 codebook bake.
__global__ __launch_bounds__(256) void vq_prep(const float* __restrict__ cb) {
    __shared__ float sc[64 * 129];
    const int tid = threadIdx.x;
    const int row0 = blockIdx.x * 64;
    for (int i = tid; i < 64 * 128; i += 256) {
        int r = i >> 7, c = i & 127;
        sc[r * 129 + c] = cb[(size_t)(row0 + r) * C_ + c];
    }
    __syncthreads();
    if (tid < 64) {
        float s = 0.f;
        for (int c = 0; c < C_; ++c) {
            float v = sc[tid * 129 + c];
            s = __fadd_rn(s, __fmul_rn(v, v));
        }
        g_bnorm[row0 + tid] = s;
        g_used[row0 + tid] = 0;
    }
    for (int i = tid; i < 64 * 128; i += 256) {
        int r = i >> 7, c = i & 127;
        g_cbq[(size_t)(row0 + r) * C_ + c] = __half_as_ushort(__float2half_rn(sc[r * 129 + c]));
    }
}

// ------------------------------------------------------------------ main
__global__ __launch_bounds__(512, 1)
void vq_main(const float* __restrict__ z, const float* __restrict__ cb,
             float* __restrict__ out) {
    extern __shared__ char smem[];
    const uint32_t smem_u = smem_u32(smem);
    const int tid = threadIdx.x;
    const int wid = tid >> 5, lane = tid & 31;

    const int tile = blockIdx.x * TOK;
    const int b = tile >> 12, hw = tile & 4095;
    const float* zbase = z + ((size_t)b * C_) * 4096 + hw;

    __half* sZ    = (__half*)(smem + OFF_Z);
    float*  pv    = (float*)(smem + OFF_PV);
    int*    pk    = (int*)(smem + OFF_PK);
    int*    idx_s = (int*)(smem + OFF_IDX);
    float*  wsum  = (float*)(smem + OFF_WS);

    // ---- stage z -> fp16, padded row-major [token][c] ----
    {
        const int t = tid & 255, h = tid >> 8;
        for (int it = 0; it < 64; ++it) {
            int c = it * 2 + h;
            sZ[t * 136 + c] = __float2half_rn(zbase[(size_t)c * 4096 + t]);
        }
    }

    #define STAGE(ch, buf) do {                                                     \
        uint32_t _d = smem_u + OFF_B + (buf) * BUFSZ;                               \
        for (int _i = tid; _i < 1024; _i += 512) {                                  \
            int _r = _i >> 4, _cs = _i & 15;                                        \
            cpa16(_d + _r * ROWB + _cs * 16,                                        \
                  g_cbq + (size_t)((ch) * NCC + _r) * C_ + _cs * 8);                \
        }                                                                           \
        if (tid < 16) cpa16(_d + NCC * ROWB + tid * 16, g_bnorm + (ch) * NCC + tid * 4); \
    } while (0)

    __syncthreads();   // sZ visible

    STAGE(0, 0);
    CPA_COMMIT();

    // ---- cache A fragments: warp w owns tokens w*16..w*16+15 ----
    uint32_t Ah[8][4];
    {
        uint32_t aZ = smem_u + OFF_Z + (wid * 16 + (lane & 15)) * ROWB + (lane >> 4) * 16;
        #pragma unroll
        for (int k = 0; k < 8; ++k)
            LDSM4(Ah[k][0], Ah[k][1], Ah[k][2], Ah[k][3], aZ + k * 32);
    }

    float v01 = 3e38f, v02 = 3e38f, v03 = 3e38f;
    float v11 = 3e38f, v12 = 3e38f, v13 = 3e38f;
    int   i01 = 0, i02 = 0, i03 = 0, i11 = 0, i12 = 0, i13 = 0;

    for (int ch = 0; ch < NCHUNK; ++ch) {
        const int buf = ch & 1;
        if (ch + 1 < NCHUNK) { STAGE(ch + 1, buf ^ 1); CPA_COMMIT(); CPA_WAIT1(); }
        else                 { CPA_WAIT0(); }
        __syncthreads();

        const uint32_t bB  = smem_u + OFF_B + buf * BUFSZ;
        const char*    bnB = smem + OFF_B + buf * BUFSZ + NCC * ROWB;

        #pragma unroll
        for (int nb = 0; nb < 8; ++nb) {
            float acc[4] = {0.f, 0.f, 0.f, 0.f};
            uint32_t ba = bB + (nb * 8 + (lane & 7)) * ROWB + (lane >> 3) * 16;
            #pragma unroll
            for (int kp = 0; kp < 4; ++kp) {
                uint32_t b0, b1, b2, b3;
                LDSM4(b0, b1, b2, b3, ba + kp * 64);
                mma_f16(acc, Ah[2 * kp],     b0, b1);
                mma_f16(acc, Ah[2 * kp + 1], b2, b3);
            }
            float2 bnv = *(const float2*)(bnB + (nb * 8 + 2 * (lane & 3)) * 4);
            int col = ch * NCC + nb * 8 + 2 * (lane & 3);
            float s;
            s = __fmaf_rn(-2.f, acc[0], bnv.x); UPD3(v01, v02, v03, i01, i02, i03, s, col);
            s = __fmaf_rn(-2.f, acc[1], bnv.y); UPD3(v01, v02, v03, i01, i02, i03, s, col + 1);
            s = __fmaf_rn(-2.f, acc[2], bnv.x); UPD3(v11, v12, v13, i11, i12, i13, s, col);
            s = __fmaf_rn(-2.f, acc[3], bnv.y); UPD3(v11, v12, v13, i11, i12, i13, s, col + 1);
        }
        __syncthreads();
    }

    // ---- publish candidates: 4 lanes x top-3 = 12 per token ----
    {
        int t0 = wid * 16 + (lane >> 2);
        int slot = (lane & 3) * 3;
        pv[(slot + 0) * TOK + t0] = v01;  pk[(slot + 0) * TOK + t0] = i01;
        pv[(slot + 1) * TOK + t0] = v02;  pk[(slot + 1) * TOK + t0] = i02;
        pv[(slot + 2) * TOK + t0] = v03;  pk[(slot + 2) * TOK + t0] = i03;
        int t1 = t0 + 8;
        pv[(slot + 0) * TOK + t1] = v11;  pk[(slot + 0) * TOK + t1] = i11;
        pv[(slot + 1) * TOK + t1] = v12;  pk[(slot + 1) * TOK + t1] = i12;
        pv[(slot + 2) * TOK + t1] = v13;  pk[(slot + 2) * TOK + t1] = i13;
    }
    __syncthreads();

    // ---- exact fp32 lattice refinement (reference-identical rounding) ----
    if (tid < TOK) {
        const int t = tid;
        float A = 0.f;
        #pragma unroll 8
        for (int c = 0; c < C_; ++c) {
            float v = zbase[(size_t)c * 4096 + t];
            A = __fadd_rn(A, __fmul_rn(v, v));
        }
        float vmin = 3.4e38f;
        #pragma unroll
        for (int q = 0; q < 12; ++q) vmin = fminf(vmin, pv[q * TOK + t]);
        float bs = 3.4e38f;
        int   bi = 0x7fffffff;
        for (int q = 0; q < 12; ++q) {
            if (pv[q * TOK + t] <= vmin + MARGIN) {
                int k = pk[q * TOK + t];
                const float* e = cb + (size_t)k * C_;
                float M = 0.f;
                #pragma unroll 8
                for (int c = 0; c < C_; ++c)
                    M = __fmaf_rn(zbase[(size_t)c * 4096 + t], __ldg(e + c), M);
                float s = __fmaf_rn(-2.f, M, __fadd_rn(A, __ldg(&g_bnorm[k])));
                if (s < bs || (s == bs && k < bi)) { bs = s; bi = k; }
            }
        }
        idx_s[t] = bi;
        g_used[bi] = 1;   // racy but idempotent -> deterministic
    }
    __syncthreads();

    // ---- epilogue: z_q_st = fl(z + fl(e - z)); loss partial ----
    float* obase = out + ((size_t)b * C_) * 4096 + hw;
    float lsum = 0.f;
    for (int i = tid; i < C_ * TOK; i += 512) {
        int c = i >> 8, t = i & 255;
        float e  = __ldg(cb + (size_t)idx_s[t] * C_ + c);
        float zz = zbase[(size_t)c * 4096 + t];
        float d  = __fsub_rn(e, zz);
        obase[(size_t)c * 4096 + t] = __fadd_rn(zz, d);
        lsum = __fmaf_rn(d, d, lsum);
    }
    #pragma unroll
    for (int o = 16; o; o >>= 1) lsum += __shfl_xor_sync(0xffffffffu, lsum, o);
    if ((tid & 31) == 0) wsum[wid] = lsum;
    __syncthreads();
    if (tid == 0) {
        float s = 0.f;
        #pragma unroll
        for (int w = 0; w < 16; ++w) s += wsum[w];
        g_partial[blockIdx.x] = s;
    }
}

// ------------------------------------------------------------------ finalize
__global__ void vq_final(float* __restrict__ out, int out_size) {
    __shared__ double ds[256];
    __shared__ int    ci[256];
    int tid = threadIdx.x;
    double s = 0.0;
    int cnt = 0;
    for (int i = tid; i < NBLK; i += 256) s += (double)g_partial[i];
    for (int i = tid; i < K_;   i += 256) cnt += (g_used[i] != 0);
    ds[tid] = s; ci[tid] = cnt;
    __syncthreads();
    for (int o = 128; o; o >>= 1) {
        if (tid < o) { ds[tid] += ds[tid + o]; ci[tid] += ci[tid + o]; }
        __syncthreads();
    }
    if (tid == 0) {
        double m = ds[0] / (double)(out_size - 2);
        out[out_size - 2] = (float)(1.25 * m);
        out[out_size - 1] = (float)ci[0] / (float)K_;
    }
}

extern "C" void kernel_launch(void* const* d_in, const int* in_sizes, int n_in,
                              void* d_out, int out_size) {
    (void)in_sizes; (void)n_in;
    const float* z  = (const float*)d_in[0];
    const float* cb = (const float*)d_in[1];
    float* out = (float*)d_out;

    cudaFuncSetAttribute(vq_main, cudaFuncAttributeMaxDynamicSharedMemorySize, SMEM_TOTAL);

    vq_prep<<<16, 256>>>(cb);
    vq_main<<<NBLK, 512, SMEM_TOTAL>>>(z, cb, out);
    vq_final<<<1, 256>>>(out, out_size);
}

// round 15
// speedup vs baseline: 4.2218x; 1.3627x over previous
#include <cuda_runtime.h>
#include <cuda_fp16.h>
#include <cstdint>
#include <cstddef>

// VectorQuantizer: single-pass fp16 HMMA candidate GEMM + exact fp32 lattice
// refinement. R12: 2 CTAs/SM (TOK=128, 256 thr), smem-staged epilogue gather,
// float4 refinement loads.
// z (16,128,64,64) f32, codebook (1024,128) f32.

#define C_     128
#define K_     1024
#define NTOK   65536
#define TOK    128
#define NBLK   (NTOK / TOK)   // 512
#define NCC    64             // codes per chunk
#define NCHUNK (K_ / NCC)     // 16
#define MARGIN 4e-4f

#define ROWB    272           // 136 halves padded row stride (conflict-free ldmatrix)
#define OFF_Z   0             // 128 x 272 = 34816
#define OFF_B   34816         // 2 x 17664 = 35328 -> 70144
#define BUFSZ   17664
#define OFF_PV  70144         // 12 x 128 x 4 = 6144
#define OFF_PK  76288         // 6144
#define OFF_IDX 82432         // 512
#define OFF_WS  82944         // 32
#define SMEM_TOTAL 82976
// sE overlay (post-refinement): 128 rows x 129 floats = 66048 bytes at OFF_Z

__device__ float g_bnorm[K_];
__device__ int   g_used[K_];
__device__ float g_partial[NBLK];
__device__ __align__(16) unsigned short g_cbq[K_ * C_];   // fp16 codebook

// ------------------------------------------------------------------ helpers
__device__ __forceinline__ uint32_t smem_u32(const void* p) {
    uint32_t a;
    asm("{ .reg .u64 t; cvta.to.shared.u64 t, %1; cvt.u32.u64 %0, t; }" : "=r"(a) : "l"(p));
    return a;
}
__device__ __forceinline__ void cpa16(uint32_t dst, const void* src) {
    asm volatile("cp.async.cg.shared.global [%0], [%1], 16;" :: "r"(dst), "l"(src) : "memory");
}
#define CPA_COMMIT() asm volatile("cp.async.commit_group;" ::: "memory")
#define CPA_WAIT1()  asm volatile("cp.async.wait_group 1;" ::: "memory")
#define CPA_WAIT0()  asm volatile("cp.async.wait_group 0;" ::: "memory")
#define LDSM4(d0,d1,d2,d3,a) \
    asm volatile("ldmatrix.sync.aligned.m8n8.x4.shared.b16 {%0,%1,%2,%3}, [%4];" \
                 : "=r"(d0),"=r"(d1),"=r"(d2),"=r"(d3) : "r"(a))
__device__ __forceinline__ void mma_f16(float acc[4], const uint32_t a[4],
                                        uint32_t b0, uint32_t b1) {
    asm volatile("mma.sync.aligned.m16n8k16.row.col.f32.f16.f16.f32 "
                 "{%0,%1,%2,%3},{%4,%5,%6,%7},{%8,%9},{%0,%1,%2,%3};"
                 : "+f"(acc[0]), "+f"(acc[1]), "+f"(acc[2]), "+f"(acc[3])
                 : "r"(a[0]), "r"(a[1]), "r"(a[2]), "r"(a[3]), "r"(b0), "r"(b1));
}
#define UPD3(V1,V2,V3,I1,I2,I3,s,kk) do {                                  \
    if ((s) < V1)      { V3=V2; I3=I2; V2=V1; I2=I1; V1=(s); I1=(kk); }    \
    else if ((s) < V2) { V3=V2; I3=I2; V2=(s); I2=(kk); }                  \
    else if ((s) < V3) { V3=(s); I3=(kk); }                                \
} while (0)

// ------------------------------------------------------------------ prep
// exact serial bnorms, usage reset, fp16 codebook bake. grid=64 x 16 rows.
__global__ __launch_bounds__(256) void vq_prep(const float* __restrict__ cb) {
    __shared__ float sc[16 * 129];
    const int tid = threadIdx.x;
    const int row0 = blockIdx.x * 16;
    for (int i = tid; i < 16 * 128; i += 256) {
        int r = i >> 7, c = i & 127;
        sc[r * 129 + c] = cb[(size_t)(row0 + r) * C_ + c];
    }
    __syncthreads();
    if (tid < 16) {
        float s = 0.f;
        for (int c = 0; c < C_; ++c) {
            float v = sc[tid * 129 + c];
            s = __fadd_rn(s, __fmul_rn(v, v));
        }
        g_bnorm[row0 + tid] = s;
        g_used[row0 + tid] = 0;
    }
    for (int i = tid; i < 16 * 128; i += 256) {
        int r = i >> 7, c = i & 127;
        g_cbq[(size_t)(row0 + r) * C_ + c] = __half_as_ushort(__float2half_rn(sc[r * 129 + c]));
    }
}

// ------------------------------------------------------------------ main
__global__ __launch_bounds__(256, 2)
void vq_main(const float* __restrict__ z, const float* __restrict__ cb,
             float* __restrict__ out) {
    extern __shared__ char smem[];
    const uint32_t smem_u = smem_u32(smem);
    const int tid = threadIdx.x;
    const int wid = tid >> 5, lane = tid & 31;

    const int tile = blockIdx.x * TOK;
    const int b = tile >> 12, hw = tile & 4095;
    const float* zbase = z + ((size_t)b * C_) * 4096 + hw;

    __half* sZ    = (__half*)(smem + OFF_Z);
    float*  pv    = (float*)(smem + OFF_PV);
    int*    pk    = (int*)(smem + OFF_PK);
    int*    idx_s = (int*)(smem + OFF_IDX);
    float*  wsum  = (float*)(smem + OFF_WS);
    float*  sE    = (float*)(smem + OFF_Z);   // overlay, used post-refinement

    // ---- stage z -> fp16, padded row-major [token][c] ----
    {
        const int t = tid & 127, h = tid >> 7;
        for (int it = 0; it < 64; ++it) {
            int c = it * 2 + h;
            sZ[t * 136 + c] = __float2half_rn(zbase[(size_t)c * 4096 + t]);
        }
    }

    #define STAGE(ch, buf) do {                                                     \
        uint32_t _d = smem_u + OFF_B + (buf) * BUFSZ;                               \
        for (int _i = tid; _i < 1024; _i += 256) {                                  \
            int _r = _i >> 4, _cs = _i & 15;                                        \
            cpa16(_d + _r * ROWB + _cs * 16,                                        \
                  g_cbq + (size_t)((ch) * NCC + _r) * C_ + _cs * 8);                \
        }                                                                           \
        if (tid < 16) cpa16(_d + NCC * ROWB + tid * 16, g_bnorm + (ch) * NCC + tid * 4); \
    } while (0)

    __syncthreads();   // sZ visible

    STAGE(0, 0);
    CPA_COMMIT();

    // ---- cache A fragments: warp w owns tokens w*16..w*16+15 ----
    uint32_t Ah[8][4];
    {
        uint32_t aZ = smem_u + OFF_Z + (wid * 16 + (lane & 15)) * ROWB + (lane >> 4) * 16;
        #pragma unroll
        for (int k = 0; k < 8; ++k)
            LDSM4(Ah[k][0], Ah[k][1], Ah[k][2], Ah[k][3], aZ + k * 32);
    }

    float v01 = 3e38f, v02 = 3e38f, v03 = 3e38f;
    float v11 = 3e38f, v12 = 3e38f, v13 = 3e38f;
    int   i01 = 0, i02 = 0, i03 = 0, i11 = 0, i12 = 0, i13 = 0;

    for (int ch = 0; ch < NCHUNK; ++ch) {
        const int buf = ch & 1;
        if (ch + 1 < NCHUNK) { STAGE(ch + 1, buf ^ 1); CPA_COMMIT(); CPA_WAIT1(); }
        else                 { CPA_WAIT0(); }
        __syncthreads();

        const uint32_t bB  = smem_u + OFF_B + buf * BUFSZ;
        const char*    bnB = smem + OFF_B + buf * BUFSZ + NCC * ROWB;

        #pragma unroll
        for (int nb = 0; nb < 8; ++nb) {
            float acc[4] = {0.f, 0.f, 0.f, 0.f};
            uint32_t ba = bB + (nb * 8 + (lane & 7)) * ROWB + (lane >> 3) * 16;
            #pragma unroll
            for (int kp = 0; kp < 4; ++kp) {
                uint32_t b0, b1, b2, b3;
                LDSM4(b0, b1, b2, b3, ba + kp * 64);
                mma_f16(acc, Ah[2 * kp],     b0, b1);
                mma_f16(acc, Ah[2 * kp + 1], b2, b3);
            }
            float2 bnv = *(const float2*)(bnB + (nb * 8 + 2 * (lane & 3)) * 4);
            int col = ch * NCC + nb * 8 + 2 * (lane & 3);
            float s;
            s = __fmaf_rn(-2.f, acc[0], bnv.x); UPD3(v01, v02, v03, i01, i02, i03, s, col);
            s = __fmaf_rn(-2.f, acc[1], bnv.y); UPD3(v01, v02, v03, i01, i02, i03, s, col + 1);
            s = __fmaf_rn(-2.f, acc[2], bnv.x); UPD3(v11, v12, v13, i11, i12, i13, s, col);
            s = __fmaf_rn(-2.f, acc[3], bnv.y); UPD3(v11, v12, v13, i11, i12, i13, s, col + 1);
        }
        __syncthreads();
    }

    // ---- publish candidates: 4 lanes x top-3 = 12 per token ----
    {
        int t0 = wid * 16 + (lane >> 2);
        int slot = (lane & 3) * 3;
        pv[(slot + 0) * TOK + t0] = v01;  pk[(slot + 0) * TOK + t0] = i01;
        pv[(slot + 1) * TOK + t0] = v02;  pk[(slot + 1) * TOK + t0] = i02;
        pv[(slot + 2) * TOK + t0] = v03;  pk[(slot + 2) * TOK + t0] = i03;
        int t1 = t0 + 8;
        pv[(slot + 0) * TOK + t1] = v11;  pk[(slot + 0) * TOK + t1] = i11;
        pv[(slot + 1) * TOK + t1] = v12;  pk[(slot + 1) * TOK + t1] = i12;
        pv[(slot + 2) * TOK + t1] = v13;  pk[(slot + 2) * TOK + t1] = i13;
    }
    __syncthreads();

    // ---- exact fp32 lattice refinement (reference-identical rounding) ----
    if (tid < TOK) {
        const int t = tid;
        float A = 0.f;
        #pragma unroll 8
        for (int c = 0; c < C_; ++c) {
            float v = zbase[(size_t)c * 4096 + t];
            A = __fadd_rn(A, __fmul_rn(v, v));
        }
        float vmin = 3.4e38f;
        #pragma unroll
        for (int q = 0; q < 12; ++q) vmin = fminf(vmin, pv[q * TOK + t]);
        float bs = 3.4e38f;
        int   bi = 0x7fffffff;
        for (int q = 0; q < 12; ++q) {
            if (pv[q * TOK + t] <= vmin + MARGIN) {
                int k = pk[q * TOK + t];
                const float4* e4 = (const float4*)(cb + (size_t)k * C_);
                float M = 0.f;
                #pragma unroll 8
                for (int c4 = 0; c4 < C_ / 4; ++c4) {
                    float4 ev = __ldg(e4 + c4);
                    int c = c4 * 4;
                    M = __fmaf_rn(zbase[(size_t)(c + 0) * 4096 + t], ev.x, M);
                    M = __fmaf_rn(zbase[(size_t)(c + 1) * 4096 + t], ev.y, M);
                    M = __fmaf_rn(zbase[(size_t)(c + 2) * 4096 + t], ev.z, M);
                    M = __fmaf_rn(zbase[(size_t)(c + 3) * 4096 + t], ev.w, M);
                }
                float s = __fmaf_rn(-2.f, M, __fadd_rn(A, __ldg(&g_bnorm[k])));
                if (s < bs || (s == bs && k < bi)) { bs = s; bi = k; }
            }
        }
        idx_s[t] = bi;
        g_used[bi] = 1;   // racy but idempotent -> deterministic
    }
    __syncthreads();

    // ---- stage winning code rows into smem, coalesced (overlay sZ/B) ----
    {
        // warp w stages rows w*16 .. w*16+15; one float4 LDG per lane per row
        for (int r = 0; r < 16; ++r) {
            int t = wid * 16 + r;
            const float4* src = (const float4*)(cb + (size_t)idx_s[t] * C_);
            float4 v = __ldg(src + lane);
            float* dst = sE + t * 129 + lane * 4;
            dst[0] = v.x; dst[1] = v.y; dst[2] = v.z; dst[3] = v.w;
        }
    }
    __syncthreads();

    // ---- epilogue: z_q_st = fl(z + fl(e - z)); loss partial ----
    float* obase = out + ((size_t)b * C_) * 4096 + hw;
    float lsum = 0.f;
    for (int i = tid; i < C_ * TOK; i += 256) {
        int c = i >> 7, t = i & 127;
        float e  = sE[t * 129 + c];
        float zz = zbase[(size_t)c * 4096 + t];
        float d  = __fsub_rn(e, zz);
        obase[(size_t)c * 4096 + t] = __fadd_rn(zz, d);
        lsum = __fmaf_rn(d, d, lsum);
    }
    #pragma unroll
    for (int o = 16; o; o >>= 1) lsum += __shfl_xor_sync(0xffffffffu, lsum, o);
    if ((tid & 31) == 0) wsum[wid] = lsum;
    __syncthreads();
    if (tid == 0) {
        float s = 0.f;
        #pragma unroll
        for (int w = 0; w < 8; ++w) s += wsum[w];
        g_partial[blockIdx.x] = s;
    }
}

// ------------------------------------------------------------------ finalize
__global__ void vq_final(float* __restrict__ out, int out_size) {
    __shared__ double ds[256];
    __shared__ int    ci[256];
    int tid = threadIdx.x;
    double s = 0.0;
    int cnt = 0;
    for (int i = tid; i < NBLK; i += 256) s += (double)g_partial[i];
    for (int i = tid; i < K_;   i += 256) cnt += (g_used[i] != 0);
    ds[tid] = s; ci[tid] = cnt;
    __syncthreads();
    for (int o = 128; o; o >>= 1) {
        if (tid < o) { ds[tid] += ds[tid + o]; ci[tid] += ci[tid + o]; }
        __syncthreads();
    }
    if (tid == 0) {
        double m = ds[0] / (double)(out_size - 2);
        out[out_size - 2] = (float)(1.25 * m);
        out[out_size - 1] = (float)ci[0] / (float)K_;
    }
}

extern "C" void kernel_launch(void* const* d_in, const int* in_sizes, int n_in,
                              void* d_out, int out_size) {
    (void)in_sizes; (void)n_in;
    const float* z  = (const float*)d_in[0];
    const float* cb = (const float*)d_in[1];
    float* out = (float*)d_out;

    cudaFuncSetAttribute(vq_main, cudaFuncAttributeMaxDynamicSharedMemorySize, SMEM_TOTAL);

    vq_prep<<<64, 256>>>(cb);
    vq_main<<<NBLK, 256, SMEM_TOTAL>>>(z, cb, out);
    vq_final<<<1, 256>>>(out, out_size);
}

// round 17
// speedup vs baseline: 4.8378x; 1.1459x over previous
#include <cuda_runtime.h>
#include <cuda_fp16.h>
#include <cstdint>
#include <cstddef>

// VectorQuantizer: single-pass fp16 HMMA candidate GEMM + exact fp32 lattice
// refinement. R15: packed (score|index) integer top-3, occ 3 via smem overlay,
// finalize fused into main kernel.
// z (16,128,64,64) f32, codebook (1024,128) f32.

#define C_     128
#define K_     1024
#define NTOK   65536
#define TOK    128
#define NBLK   (NTOK / TOK)   // 512
#define NCC    64             // codes per chunk
#define NCHUNK (K_ / NCC)     // 16
#define MARGIN 1.2e-3f        // covers fp16 GEMM err + 10-bit packing quantization

#define ROWB    272           // 136 halves padded row stride (conflict-free ldmatrix)
#define OFF_Z   0             // 128 x 272 = 34816
#define OFF_B   34816         // 2 x 17664 = 35328 -> end 70144
#define BUFSZ   17664         // 64*272 B rows + 256 bnp1
#define OFF_PU  34816         // overlay on B (post-mainloop): 12 x 128 x 4 = 6144
#define OFF_IDX 70144         // 512
#define OFF_WS  70656         // 32
#define SMEM_TOTAL 70688
// sE overlay (post-refinement): 128 x 129 floats = 66048 bytes at OFF_Z

__device__ float g_bnorm[K_];     // exact ||e||^2 (refinement)
__device__ float g_bnp1[K_];      // ||e||^2 + 1   (packed approx domain)
__device__ int   g_used[K_];
__device__ float g_partial[NBLK];
__device__ unsigned int g_done;   // zero-init; self-resetting
__device__ __align__(16) unsigned short g_cbq[K_ * C_];   // fp16 codebook

// ------------------------------------------------------------------ helpers
__device__ __forceinline__ uint32_t smem_u32(const void* p) {
    uint32_t a;
    asm("{ .reg .u64 t; cvta.to.shared.u64 t, %1; cvt.u32.u64 %0, t; }" : "=r"(a) : "l"(p));
    return a;
}
__device__ __forceinline__ void cpa16(uint32_t dst, const void* src) {
    asm volatile("cp.async.cg.shared.global [%0], [%1], 16;" :: "r"(dst), "l"(src) : "memory");
}
#define CPA_COMMIT() asm volatile("cp.async.commit_group;" ::: "memory")
#define CPA_WAIT1()  asm volatile("cp.async.wait_group 1;" ::: "memory")
#define CPA_WAIT0()  asm volatile("cp.async.wait_group 0;" ::: "memory")
#define LDSM4(d0,d1,d2,d3,a) \
    asm volatile("ldmatrix.sync.aligned.m8n8.x4.shared.b16 {%0,%1,%2,%3}, [%4];" \
                 : "=r"(d0),"=r"(d1),"=r"(d2),"=r"(d3) : "r"(a))
__device__ __forceinline__ void mma_f16(float acc[4], const uint32_t a[4],
                                        uint32_t b0, uint32_t b1) {
    asm volatile("mma.sync.aligned.m16n8k16.row.col.f32.f16.f16.f32 "
                 "{%0,%1,%2,%3},{%4,%5,%6,%7},{%8,%9},{%0,%1,%2,%3};"
                 : "+f"(acc[0]), "+f"(acc[1]), "+f"(acc[2]), "+f"(acc[3])
                 : "r"(a[0]), "r"(a[1]), "r"(a[2]), "r"(a[3]), "r"(b0), "r"(b1));
}
// packed insertion into ascending top-3 (uint compare == float compare, >0 floats)
#define INS3(m1,m2,m3,uv) do {                                   \
    uint32_t _x = (uv), _t;                                      \
    _t = umin(m1,_x); _x = umax(m1,_x); m1 = _t;                 \
    _t = umin(m2,_x); _x = umax(m2,_x); m2 = _t;                 \
    m3 = umin(m3,_x);                                            \
} while (0)

// ------------------------------------------------------------------ prep
__global__ __launch_bounds__(256) void vq_prep(const float* __restrict__ cb) {
    __shared__ float sc[16 * 129];
    const int tid = threadIdx.x;
    const int row0 = blockIdx.x * 16;
    for (int i = tid; i < 16 * 128; i += 256) {
        int r = i >> 7, c = i & 127;
        sc[r * 129 + c] = cb[(size_t)(row0 + r) * C_ + c];
    }
    __syncthreads();
    if (tid < 16) {
        float s = 0.f;
        for (int c = 0; c < C_; ++c) {
            float v = sc[tid * 129 + c];
            s = __fadd_rn(s, __fmul_rn(v, v));
        }
        g_bnorm[row0 + tid] = s;
        g_bnp1[row0 + tid]  = __fadd_rn(s, 1.f);
        g_used[row0 + tid] = 0;
    }
    for (int i = tid; i < 16 * 128; i += 256) {
        int r = i >> 7, c = i & 127;
        g_cbq[(size_t)(row0 + r) * C_ + c] = __half_as_ushort(__float2half_rn(sc[r * 129 + c]));
    }
}

// ------------------------------------------------------------------ main
__global__ __launch_bounds__(256, 3)
void vq_main(const float* __restrict__ z, const float* __restrict__ cb,
             float* __restrict__ out, int out_size) {
    extern __shared__ char smem[];
    const uint32_t smem_u = smem_u32(smem);
    const int tid = threadIdx.x;
    const int wid = tid >> 5, lane = tid & 31;

    const int tile = blockIdx.x * TOK;
    const int b = tile >> 12, hw = tile & 4095;
    const float* zbase = z + ((size_t)b * C_) * 4096 + hw;

    __half*    sZ    = (__half*)(smem + OFF_Z);
    uint32_t*  pu    = (uint32_t*)(smem + OFF_PU);
    int*       idx_s = (int*)(smem + OFF_IDX);
    float*     wsum  = (float*)(smem + OFF_WS);
    float*     sE    = (float*)(smem + OFF_Z);   // overlay, post-refinement

    // ---- stage z -> fp16, padded row-major [token][c] ----
    {
        const int t = tid & 127, h = tid >> 7;
        for (int it = 0; it < 64; ++it) {
            int c = it * 2 + h;
            sZ[t * 136 + c] = __float2half_rn(zbase[(size_t)c * 4096 + t]);
        }
    }

    #define STAGE(ch, buf) do {                                                     \
        uint32_t _d = smem_u + OFF_B + (buf) * BUFSZ;                               \
        for (int _i = tid; _i < 1024; _i += 256) {                                  \
            int _r = _i >> 4, _cs = _i & 15;                                        \
            cpa16(_d + _r * ROWB + _cs * 16,                                        \
                  g_cbq + (size_t)((ch) * NCC + _r) * C_ + _cs * 8);                \
        }                                                                           \
        if (tid < 16) cpa16(_d + NCC * ROWB + tid * 16, g_bnp1 + (ch) * NCC + tid * 4); \
    } while (0)

    __syncthreads();   // sZ visible

    STAGE(0, 0);
    CPA_COMMIT();

    // ---- cache A fragments: warp w owns tokens w*16..w*16+15 ----
    uint32_t Ah[8][4];
    {
        uint32_t aZ = smem_u + OFF_Z + (wid * 16 + (lane & 15)) * ROWB + (lane >> 4) * 16;
        #pragma unroll
        for (int k = 0; k < 8; ++k)
            LDSM4(Ah[k][0], Ah[k][1], Ah[k][2], Ah[k][3], aZ + k * 32);
    }

    // packed top-3 per lane, rows 0 / 1 (+8)
    uint32_t a1 = 0xFFFFFFFFu, a2 = 0xFFFFFFFFu, a3 = 0xFFFFFFFFu;
    uint32_t b1 = 0xFFFFFFFFu, b2 = 0xFFFFFFFFu, b3 = 0xFFFFFFFFu;

    for (int ch = 0; ch < NCHUNK; ++ch) {
        const int buf = ch & 1;
        if (ch + 1 < NCHUNK) { STAGE(ch + 1, buf ^ 1); CPA_COMMIT(); CPA_WAIT1(); }
        else                 { CPA_WAIT0(); }
        __syncthreads();

        const uint32_t bB  = smem_u + OFF_B + buf * BUFSZ;
        const char*    bnB = smem + OFF_B + buf * BUFSZ + NCC * ROWB;
        const uint32_t kc  = (uint32_t)(ch * NCC + 2 * (lane & 3));

        #pragma unroll
        for (int nb = 0; nb < 8; ++nb) {
            float acc[4] = {0.f, 0.f, 0.f, 0.f};
            uint32_t ba = bB + (nb * 8 + (lane & 7)) * ROWB + (lane >> 3) * 16;
            #pragma unroll
            for (int kp = 0; kp < 4; ++kp) {
                uint32_t q0, q1, q2, q3;
                LDSM4(q0, q1, q2, q3, ba + kp * 64);
                mma_f16(acc, Ah[2 * kp],     q0, q1);
                mma_f16(acc, Ah[2 * kp + 1], q2, q3);
            }
            float2 bnv = *(const float2*)(bnB + (nb * 8 + 2 * (lane & 3)) * 4);
            uint32_t k0 = kc + nb * 8;
            float s;
            s = __fmaf_rn(-2.f, acc[0], bnv.x);
            INS3(a1, a2, a3, (__float_as_uint(s) & 0xFFFFFC00u) | k0);
            s = __fmaf_rn(-2.f, acc[1], bnv.y);
            INS3(a1, a2, a3, (__float_as_uint(s) & 0xFFFFFC00u) | (k0 + 1));
            s = __fmaf_rn(-2.f, acc[2], bnv.x);
            INS3(b1, b2, b3, (__float_as_uint(s) & 0xFFFFFC00u) | k0);
            s = __fmaf_rn(-2.f, acc[3], bnv.y);
            INS3(b1, b2, b3, (__float_as_uint(s) & 0xFFFFFC00u) | (k0 + 1));
        }
        __syncthreads();
    }

    // ---- publish packed candidates: 4 lanes x top-3 = 12 per token ----
    {
        int t0 = wid * 16 + (lane >> 2);
        int slot = (lane & 3) * 3;
        pu[(slot + 0) * TOK + t0] = a1;
        pu[(slot + 1) * TOK + t0] = a2;
        pu[(slot + 2) * TOK + t0] = a3;
        int t1 = t0 + 8;
        pu[(slot + 0) * TOK + t1] = b1;
        pu[(slot + 1) * TOK + t1] = b2;
        pu[(slot + 2) * TOK + t1] = b3;
    }
    __syncthreads();

    // ---- exact fp32 lattice refinement (reference-identical rounding) ----
    if (tid < TOK) {
        const int t = tid;
        float A = 0.f;
        #pragma unroll 8
        for (int c = 0; c < C_; ++c) {
            float v = zbase[(size_t)c * 4096 + t];
            A = __fadd_rn(A, __fmul_rn(v, v));
        }
        uint32_t um = 0xFFFFFFFFu;
        #pragma unroll
        for (int q = 0; q < 12; ++q) um = umin(um, pu[q * TOK + t]);
        float fm = __uint_as_float(um & 0xFFFFFC00u);   // quantized (s_min + 1)
        float bs = 3.4e38f;
        int   bi = 0x7fffffff;
        for (int q = 0; q < 12; ++q) {
            uint32_t u = pu[q * TOK + t];
            float f = __uint_as_float(u & 0xFFFFFC00u);
            if (f <= fm + MARGIN) {
                int k = (int)(u & 1023u);
                const float4* e4 = (const float4*)(cb + (size_t)k * C_);
                float M = 0.f;
                #pragma unroll 8
                for (int c4 = 0; c4 < C_ / 4; ++c4) {
                    float4 ev = __ldg(e4 + c4);
                    int c = c4 * 4;
                    M = __fmaf_rn(zbase[(size_t)(c + 0) * 4096 + t], ev.x, M);
                    M = __fmaf_rn(zbase[(size_t)(c + 1) * 4096 + t], ev.y, M);
                    M = __fmaf_rn(zbase[(size_t)(c + 2) * 4096 + t], ev.z, M);
                    M = __fmaf_rn(zbase[(size_t)(c + 3) * 4096 + t], ev.w, M);
                }
                float s = __fmaf_rn(-2.f, M, __fadd_rn(A, __ldg(&g_bnorm[k])));
                if (s < bs || (s == bs && k < bi)) { bs = s; bi = k; }
            }
        }
        idx_s[t] = bi;
        g_used[bi] = 1;   // racy but idempotent -> deterministic
    }
    __syncthreads();

    // ---- stage winning code rows into smem, coalesced (overlay sZ/pu) ----
    for (int r = 0; r < 16; ++r) {
        int t = wid * 16 + r;
        const float4* src = (const float4*)(cb + (size_t)idx_s[t] * C_);
        float4 v = __ldg(src + lane);
        float* dst = sE + t * 129 + lane * 4;
        dst[0] = v.x; dst[1] = v.y; dst[2] = v.z; dst[3] = v.w;
    }
    __syncthreads();

    // ---- epilogue: z_q_st = fl(z + fl(e - z)); loss partial ----
    float* obase = out + ((size_t)b * C_) * 4096 + hw;
    float lsum = 0.f;
    for (int i = tid; i < C_ * TOK; i += 256) {
        int c = i >> 7, t = i & 127;
        float e  = sE[t * 129 + c];
        float zz = zbase[(size_t)c * 4096 + t];
        float d  = __fsub_rn(e, zz);
        obase[(size_t)c * 4096 + t] = __fadd_rn(zz, d);
        lsum = __fmaf_rn(d, d, lsum);
    }
    #pragma unroll
    for (int o = 16; o; o >>= 1) lsum += __shfl_xor_sync(0xffffffffu, lsum, o);
    if ((tid & 31) == 0) wsum[wid] = lsum;
    __syncthreads();
    if (tid == 0) {
        float s = 0.f;
        #pragma unroll
        for (int w = 0; w < 8; ++w) s += wsum[w];
        g_partial[blockIdx.x] = s;
    }

    // ---- last-CTA finalize (deterministic fixed-order reduction) ----
    __shared__ unsigned int s_last;
    __threadfence();
    if (tid == 0) s_last = (atomicAdd(&g_done, 1u) == NBLK - 1) ? 1u : 0u;
    __syncthreads();
    if (s_last) {
        double* ds = (double*)(smem + OFF_Z);          // scratch overlay
        int*    ci = (int*)(smem + OFF_Z + 2048);
        double s = 0.0;
        int cnt = 0;
        for (int i = tid; i < NBLK; i += 256) s += (double)g_partial[i];
        for (int i = tid; i < K_;   i += 256) cnt += (g_used[i] != 0);
        ds[tid] = s; ci[tid] = cnt;
        __syncthreads();
        for (int o = 128; o; o >>= 1) {
            if (tid < o) { ds[tid] += ds[tid + o]; ci[tid] += ci[tid + o]; }
            __syncthreads();
        }
        if (tid == 0) {
            double m = ds[0] / (double)(out_size - 2);
            out[out_size - 2] = (float)(1.25 * m);
            out[out_size - 1] = (float)ci[0] / (float)K_;
            g_done = 0;   // reset for next graph replay
        }
    }
}

extern "C" void kernel_launch(void* const* d_in, const int* in_sizes, int n_in,
                              void* d_out, int out_size) {
    (void)in_sizes; (void)n_in;
    const float* z  = (const float*)d_in[0];
    const float* cb = (const float*)d_in[1];
    float* out = (float*)d_out;

    cudaFuncSetAttribute(vq_main, cudaFuncAttributeMaxDynamicSharedMemorySize, SMEM_TOTAL);

    vq_prep<<<64, 256>>>(cb);
    vq_main<<<NBLK, 256, SMEM_TOTAL>>>(z, cb, out, out_size);
}